// round 8
// baseline (speedup 1.0000x reference)
#include <cuda_runtime.h>
#include <cuda_bf16.h>
#include <math.h>
#include <stdint.h>

// Problem constants
#define Bb   64
#define Dd   512
#define Vv   512
#define Oo   720
#define Ee   8
#define NTOK    (Bb*Vv)        // 32768 tokens
#define NASSIGN (NTOK*2)       // 65536 assignments (top_k = 2)
#define TILE_M  256
#define TILE_N  144            // 720 = 5 * 144
#define MAX_TILES (NASSIGN/TILE_M + Ee)   // 264
#define ROWS_CAP  (MAX_TILES*TILE_M)
#define NSTAGE 3
#define NKCHUNK (Dd/32)        // 16
// swizzled stage: (256+144) rows x 128 B
#define STAGE_BYTES ((TILE_M + TILE_N) * 128)   // 51200
#define B_OFF (TILE_M*128)                      // 32768

// ---------------- static device scratch ----------------
__device__ float g_XT[NTOK*Dd];          // tokens [B*V][D], tf32-rounded (RNA)
__device__ float g_part[2][NTOK*Oo];     // per-slot partial outputs
__device__ int   g_rows[ROWS_CAP];
__device__ float g_roww[ROWS_CAP];
__device__ int   g_counts[Ee];           // zero-initialized; k2 re-zeros each call
__device__ int   g_cursor[Ee];
__device__ int   g_tile_e[MAX_TILES];
__device__ int   g_tile_r0[MAX_TILES];
__device__ int   g_ntiles;
__device__ int   g_sel[NASSIGN];
__device__ float g_wsel[NASSIGN];

__device__ __forceinline__ float to_tf32(float x) {
    float r; asm("cvt.rna.tf32.f32 %0, %1;" : "=f"(r) : "f"(x)); return r;
}
__device__ __forceinline__ void cp16(void* smem_ptr, const void* gptr, bool valid) {
    uint32_t saddr = (uint32_t)__cvta_generic_to_shared(smem_ptr);
    int sz = valid ? 16 : 0;
    asm volatile("cp.async.cg.shared.global [%0], [%1], 16, %2;\n"
                 :: "r"(saddr), "l"(gptr), "r"(sz));
}
__device__ __forceinline__ void ldsm4(uint32_t& r0, uint32_t& r1, uint32_t& r2, uint32_t& r3,
                                      uint32_t addr) {
    asm volatile("ldmatrix.sync.aligned.m8n8.x4.shared.b16 {%0,%1,%2,%3}, [%4];"
                 : "=r"(r0), "=r"(r1), "=r"(r2), "=r"(r3) : "r"(addr));
}
__device__ __forceinline__ void ldsm2(uint32_t& r0, uint32_t& r1, uint32_t addr) {
    asm volatile("ldmatrix.sync.aligned.m8n8.x2.shared.b16 {%0,%1}, [%2];"
                 : "=r"(r0), "=r"(r1) : "r"(addr));
}

// ---------------- K1: fused transpose + gating + softmax + top-2 ----------------
__global__ void k1_gate(const float* __restrict__ x, const float* __restrict__ Wg) {
    __shared__ float sWg[Ee*Dd];
    __shared__ float sX[32][129];
    const int b  = blockIdx.y;
    const int v0 = blockIdx.x * 128;
    const int tid = threadIdx.x;
    const int wq = tid >> 5, lane = tid & 31;

    for (int i = tid; i < Ee*Dd; i += 128) sWg[i] = Wg[i];
    __syncthreads();

    float lg[Ee];
#pragma unroll
    for (int e = 0; e < Ee; e++) lg[e] = 0.f;

    for (int dc = 0; dc < Dd/32; dc++) {
#pragma unroll
        for (int i = 0; i < 32; i++)
            sX[i][tid] = x[((size_t)b*Dd + dc*32 + i)*Vv + v0 + tid];
        __syncthreads();
#pragma unroll
        for (int i = 0; i < 32; i++) {
            float xv = sX[i][tid];
            int d = dc*32 + i;
#pragma unroll
            for (int e = 0; e < Ee; e++) lg[e] += xv * sWg[e*Dd + d];
        }
#pragma unroll
        for (int r = 0; r < 32; r++) {
            int v = wq*32 + r;
            g_XT[((size_t)(b*Vv + v0 + v))*Dd + dc*32 + lane] = to_tf32(sX[lane][v]);
        }
        __syncthreads();
    }

    float m = lg[0];
#pragma unroll
    for (int e = 1; e < Ee; e++) m = fmaxf(m, lg[e]);
    float p[Ee], s = 0.f;
#pragma unroll
    for (int e = 0; e < Ee; e++) { p[e] = expf(lg[e] - m); s += p[e]; }
    float inv = 1.f / s;
#pragma unroll
    for (int e = 0; e < Ee; e++) p[e] *= inv;

    int i1 = 0;
#pragma unroll
    for (int e = 1; e < Ee; e++) if (p[e] > p[i1]) i1 = e;
    int i2 = (i1 == 0) ? 1 : 0;
#pragma unroll
    for (int e = 0; e < Ee; e++) if (e != i1 && p[e] > p[i2]) i2 = e;

    int t = b*Vv + v0 + tid;
    g_sel[2*t + 0] = i1;  g_wsel[2*t + 0] = p[i1];
    g_sel[2*t + 1] = i2;  g_wsel[2*t + 1] = p[i2];
    atomicAdd(&g_counts[i1], 1);
    atomicAdd(&g_counts[i2], 1);
}

// ---------------- K2: plan tiles; re-zero counters ----------------
__global__ void k2_plan() {
    if (threadIdx.x != 0 || blockIdx.x != 0) return;
    int base = 0, nt = 0;
    for (int e = 0; e < Ee; e++) {
        int cnt = g_counts[e];
        g_counts[e] = 0;
        g_cursor[e] = base;
        int t = (cnt + TILE_M - 1) / TILE_M;
        for (int i = 0; i < t; i++) { g_tile_e[nt] = e; g_tile_r0[nt] = base + i*TILE_M; nt++; }
        for (int pq = base + cnt; pq < base + t*TILE_M; pq++) g_rows[pq] = -1;
        base += t*TILE_M;
    }
    g_ntiles = nt;
}

// ---------------- K3: block-aggregated scatter ----------------
__global__ void k3_scatter() {
    __shared__ int hcnt[Ee];
    __shared__ int hbase[Ee];
    const int tid = threadIdx.x;
    const int t = blockIdx.x * blockDim.x + tid;
    if (tid < Ee) hcnt[tid] = 0;
    __syncthreads();
    int e1 = 0, e2 = 0, p1 = 0, p2 = 0;
    float w1 = 0.f, w2 = 0.f;
    if (t < NTOK) {
        e1 = g_sel[2*t + 0];  w1 = g_wsel[2*t + 0];
        e2 = g_sel[2*t + 1];  w2 = g_wsel[2*t + 1];
        p1 = atomicAdd(&hcnt[e1], 1);
        p2 = atomicAdd(&hcnt[e2], 1);
    }
    __syncthreads();
    if (tid < Ee) hbase[tid] = atomicAdd(&g_cursor[tid], hcnt[tid]);
    __syncthreads();
    if (t < NTOK) {
        int q1 = hbase[e1] + p1;
        int q2 = hbase[e2] + p2;
        g_rows[q1] = 2*t + 0;  g_roww[q1] = w1;
        g_rows[q2] = 2*t + 1;  g_roww[q2] = w2;
    }
}

// ---------------- K4: grouped GEMM, 256x144 tile, warp tile 64x72, 1 CTA/SM ----------------
__global__ __launch_bounds__(256, 1) void k4_gemm(const float* __restrict__ We,
                                                  const float* __restrict__ be) {
    const int mt = blockIdx.y;
    if (mt >= g_ntiles) return;
    const int o0 = blockIdx.x * TILE_N;

    extern __shared__ __align__(128) char sm[];   // NSTAGE * STAGE_BYTES
    __shared__ int   sTok[TILE_M];
    __shared__ float sW[TILE_M];
    __shared__ float sBias[TILE_N];

    const int tid  = threadIdx.x;
    const int lane = tid & 31, w = tid >> 5;
    const int wm = w & 3, wn = w >> 2;          // 4(M) x 2(N); warp tile 64 x 72
    const int g  = lane >> 2, tg = lane & 3;

    const int e  = g_tile_e[mt];
    const int r0 = g_tile_r0[mt];
    const float* WeE = We + (size_t)e*Oo*Dd;

    sTok[tid] = g_rows[r0 + tid];               // TILE_M == blockDim
    sW[tid]   = g_roww[r0 + tid];
    if (tid < TILE_N) sBias[tid] = be[e*Oo + o0 + tid];
    __syncthreads();

    // swizzled stage loader: row r (128B), unit u (16B) -> offset r*128 + ((u^(r&7))<<4)
    auto load_stage = [&](int kc, int st) {
        char* As = sm + st*STAGE_BYTES;
        char* Bs = As + B_OFF;
        const int kb = kc*32;
#pragma unroll
        for (int j = 0; j < 8; j++) {             // A: 256 rows x 8 units
            int q = tid + j*256;
            int r = q >> 3, u = q & 7;
            int tk = sTok[r];
            const float* src = (tk >= 0) ? (g_XT + (size_t)(tk >> 1)*Dd + kb + u*4) : g_XT;
            cp16(As + r*128 + ((u ^ (r & 7)) << 4), src, tk >= 0);
        }
#pragma unroll
        for (int j = 0; j < 5; j++) {             // B: 144 rows x 8 units
            int q = tid + j*256;
            if (q < TILE_N*8) {
                int r = q >> 3, u = q & 7;
                cp16(Bs + r*128 + ((u ^ (r & 7)) << 4),
                     WeE + (size_t)(o0 + r)*Dd + kb + u*4, true);
            }
        }
    };

    // ---- per-lane ldmatrix row bases + swizzle keys ----
    const uint32_t sm0 = (uint32_t)__cvta_generic_to_shared(sm);
    const int rA = lane & 7;
    const int aRowSel = ((lane >> 3) & 1) * 8;    // A tiles 1,3 -> +8 rows
    const uint32_t uhA = (lane >> 4) << 4;        // A tiles 2,3 -> +1 unit
    uint32_t aRowOff[4], aXor[4];
#pragma unroll
    for (int mf = 0; mf < 4; mf++) {
        int row = wm*64 + mf*16 + aRowSel + rA;
        aRowOff[mf] = sm0 + row*128;
        aXor[mf] = (uint32_t)((row & 7) << 4);
    }
    const int bRowSel = (lane >> 4) * 8;          // B tiles 2,3 -> +8 rows (next nf)
    const uint32_t uhB = ((lane >> 3) & 1) << 4;  // B tiles 1,3 -> +1 unit
    uint32_t bRowOff[4], bXor[4];
#pragma unroll
    for (int p = 0; p < 4; p++) {
        int row = wn*72 + p*16 + bRowSel + rA;
        bRowOff[p] = sm0 + B_OFF + row*128;
        bXor[p] = (uint32_t)((row & 7) << 4);
    }
    uint32_t b8RowOff, b8Xor;
    {
        int row = wn*72 + 64 + rA;
        b8RowOff = sm0 + B_OFF + row*128;
        b8Xor = (uint32_t)((row & 7) << 4);
    }

    float acc[4][9][4];
#pragma unroll
    for (int mf = 0; mf < 4; mf++)
#pragma unroll
        for (int nf = 0; nf < 9; nf++)
#pragma unroll
            for (int i = 0; i < 4; i++) acc[mf][nf][i] = 0.f;

    load_stage(0, 0);
    asm volatile("cp.async.commit_group;\n");
    load_stage(1, 1);
    asm volatile("cp.async.commit_group;\n");

    for (int kc = 0; kc < NKCHUNK; kc++) {
        const int st = kc % NSTAGE;
        asm volatile("cp.async.wait_group 1;\n");   // stage kc complete; kc+1 may fly
        __syncthreads();

        if (kc + 2 < NKCHUNK) load_stage(kc + 2, (kc + 2) % NSTAGE);
        asm volatile("cp.async.commit_group;\n");

        const uint32_t stOff = (uint32_t)(st*STAGE_BYTES);

#pragma unroll
        for (int ks = 0; ks < 4; ks++) {
            const uint32_t kuA = uhA + ks*32;
            const uint32_t kuB = uhB + ks*32;
            uint32_t a[4][4], bf[9][2];
#pragma unroll
            for (int p = 0; p < 4; p++)
                ldsm4(bf[2*p][0], bf[2*p][1], bf[2*p+1][0], bf[2*p+1][1],
                      bRowOff[p] + stOff + (kuB ^ bXor[p]));
            ldsm2(bf[8][0], bf[8][1], b8RowOff + stOff + (kuB ^ b8Xor));
#pragma unroll
            for (int mf = 0; mf < 4; mf++)
                ldsm4(a[mf][0], a[mf][1], a[mf][2], a[mf][3],
                      aRowOff[mf] + stOff + (kuA ^ aXor[mf]));

#pragma unroll
            for (int mf = 0; mf < 4; mf++)
#pragma unroll
                for (int nf = 0; nf < 9; nf++) {
                    float* c = acc[mf][nf];
                    asm volatile(
                        "mma.sync.aligned.m16n8k8.row.col.f32.tf32.tf32.f32 "
                        "{%0,%1,%2,%3}, {%4,%5,%6,%7}, {%8,%9}, {%0,%1,%2,%3};\n"
                        : "+f"(c[0]), "+f"(c[1]), "+f"(c[2]), "+f"(c[3])
                        : "r"(a[mf][0]), "r"(a[mf][1]), "r"(a[mf][2]), "r"(a[mf][3]),
                          "r"(bf[nf][0]), "r"(bf[nf][1]));
                }
        }
    }

    // epilogue: out = coef * (acc + bias) into slot-partial buffers (deterministic)
#pragma unroll
    for (int mf = 0; mf < 4; mf++) {
#pragma unroll
        for (int nf = 0; nf < 9; nf++) {
            int c = wn*72 + nf*8 + tg*2;
            int o = o0 + c;
#pragma unroll
            for (int h = 0; h < 2; h++) {
                int r = wm*64 + mf*16 + g + h*8;
                int tk = sTok[r];
                if (tk < 0) continue;
                float wv = sW[r];
                float2 v;
                v.x = wv * (acc[mf][nf][h*2 + 0] + sBias[c]);
                v.y = wv * (acc[mf][nf][h*2 + 1] + sBias[c + 1]);
                *(float2*)(&g_part[tk & 1][(size_t)(tk >> 1)*Oo + o]) = v;
            }
        }
    }
}

// ---------------- K5: sum slot partials + transpose [B,V,O] -> [B,O,V] ----------------
__global__ void k5_out(float* __restrict__ out) {
    __shared__ float s[32][33];
    const int b = blockIdx.z, v0 = blockIdx.x*32, o0 = blockIdx.y*32;
    const int tx = threadIdx.x, ty = threadIdx.y;
#pragma unroll
    for (int i = 0; i < 4; i++) {
        int vy = ty + i*8;
        int o = o0 + tx;
        if (o < Oo) {
            size_t idx = (size_t)(b*Vv + v0 + vy)*Oo + o;
            s[vy][tx] = g_part[0][idx] + g_part[1][idx];
        }
    }
    __syncthreads();
#pragma unroll
    for (int i = 0; i < 4; i++) {
        int oy = ty + i*8;
        if (o0 + oy < Oo)
            out[((size_t)b*Oo + o0 + oy)*Vv + v0 + tx] = s[tx][oy];
    }
}

// ---------------- launch ----------------
extern "C" void kernel_launch(void* const* d_in, const int* in_sizes, int n_in,
                              void* d_out, int out_size) {
    const float* x  = (const float*)d_in[0];
    const float* Wg = (const float*)d_in[1];
    const float* We = (const float*)d_in[2];
    const float* be = (const float*)d_in[3];
    float* out = (float*)d_out;

    static int smem_set = 0;
    const int k4_smem = NSTAGE * STAGE_BYTES;   // 153600 B
    if (!smem_set) {
        cudaFuncSetAttribute(k4_gemm, cudaFuncAttributeMaxDynamicSharedMemorySize, k4_smem);
        smem_set = 1;
    }

    k1_gate<<<dim3(Vv/128, Bb), 128>>>(x, Wg);
    k2_plan<<<1, 32>>>();
    k3_scatter<<<(NTOK + 255)/256, 256>>>();
    k4_gemm<<<dim3(5, MAX_TILES), 256, k4_smem>>>(We, be);
    k5_out<<<dim3(Vv/32, (Oo + 31)/32, Bb), dim3(32, 8)>>>(out);
}

// round 9
// speedup vs baseline: 2.1100x; 2.1100x over previous
#include <cuda_runtime.h>
#include <cuda_fp16.h>
#include <math.h>
#include <stdint.h>

// Problem constants
#define Bb   64
#define Dd   512
#define Vv   512
#define Oo   720
#define Ee   8
#define NTOK    (Bb*Vv)        // 32768 tokens
#define NASSIGN (NTOK*2)       // 65536 assignments (top_k = 2)
#define TILE_M  128
#define TILE_N  144            // 720 = 5 * 144
#define MAX_TILES (NASSIGN/TILE_M + Ee)   // 520
#define ROWS_CAP  (MAX_TILES*TILE_M)
#define NSTAGE 3
#define KCH   64               // K elements per chunk (fp16: 128 B rows)
#define NKCHUNK (Dd/KCH)       // 8
// swizzled stage: (128+144) rows x 128 B
#define STAGE_BYTES ((TILE_M + TILE_N) * 128)   // 34816
#define B_OFF (TILE_M*128)                      // 16384

// ---------------- static device scratch ----------------
__device__ __half g_XTh[NTOK*Dd];        // tokens [B*V][D], fp16
__device__ __half g_Weh[Ee*Oo*Dd];       // expert weights, fp16
__device__ float  g_part[2][NTOK*Oo];    // per-slot partial outputs
__device__ int    g_rows[ROWS_CAP];
__device__ float  g_roww[ROWS_CAP];
__device__ int    g_counts[Ee];          // zero-init; k2 re-zeros each call
__device__ int    g_cursor[Ee];
__device__ int    g_tile_e[MAX_TILES];
__device__ int    g_tile_r0[MAX_TILES];
__device__ int    g_ntiles;
__device__ int    g_sel[NASSIGN];
__device__ float  g_wsel[NASSIGN];

__device__ __forceinline__ void cp16(void* smem_ptr, const void* gptr, bool valid) {
    uint32_t saddr = (uint32_t)__cvta_generic_to_shared(smem_ptr);
    int sz = valid ? 16 : 0;
    asm volatile("cp.async.cg.shared.global [%0], [%1], 16, %2;\n"
                 :: "r"(saddr), "l"(gptr), "r"(sz));
}
__device__ __forceinline__ void ldsm4(uint32_t& r0, uint32_t& r1, uint32_t& r2, uint32_t& r3,
                                      uint32_t addr) {
    asm volatile("ldmatrix.sync.aligned.m8n8.x4.shared.b16 {%0,%1,%2,%3}, [%4];"
                 : "=r"(r0), "=r"(r1), "=r"(r2), "=r"(r3) : "r"(addr));
}
__device__ __forceinline__ void ldsm2(uint32_t& r0, uint32_t& r1, uint32_t addr) {
    asm volatile("ldmatrix.sync.aligned.m8n8.x2.shared.b16 {%0,%1}, [%2];"
                 : "=r"(r0), "=r"(r1) : "r"(addr));
}

// ---------------- K0: convert We to fp16 ----------------
__global__ void k0_prep(const float* __restrict__ We) {
    int i = blockIdx.x * blockDim.x + threadIdx.x;
    if (i < Ee*Oo*Dd) g_Weh[i] = __float2half(We[i]);
}

// ---------------- K1: fused transpose + gating + softmax + top-2 ----------------
__global__ void k1_gate(const float* __restrict__ x, const float* __restrict__ Wg) {
    __shared__ float sWg[Ee*Dd];
    __shared__ float sX[32][129];
    const int b  = blockIdx.y;
    const int v0 = blockIdx.x * 128;
    const int tid = threadIdx.x;
    const int wq = tid >> 5, lane = tid & 31;

    for (int i = tid; i < Ee*Dd; i += 128) sWg[i] = Wg[i];
    __syncthreads();

    float lg[Ee];
#pragma unroll
    for (int e = 0; e < Ee; e++) lg[e] = 0.f;

    for (int dc = 0; dc < Dd/32; dc++) {
#pragma unroll
        for (int i = 0; i < 32; i++)
            sX[i][tid] = x[((size_t)b*Dd + dc*32 + i)*Vv + v0 + tid];
        __syncthreads();
#pragma unroll
        for (int i = 0; i < 32; i++) {
            float xv = sX[i][tid];
            int d = dc*32 + i;
#pragma unroll
            for (int e = 0; e < Ee; e++) lg[e] += xv * sWg[e*Dd + d];
        }
#pragma unroll
        for (int r = 0; r < 32; r++) {
            int v = wq*32 + r;
            g_XTh[((size_t)(b*Vv + v0 + v))*Dd + dc*32 + lane] = __float2half(sX[lane][v]);
        }
        __syncthreads();
    }

    float m = lg[0];
#pragma unroll
    for (int e = 1; e < Ee; e++) m = fmaxf(m, lg[e]);
    float p[Ee], s = 0.f;
#pragma unroll
    for (int e = 0; e < Ee; e++) { p[e] = expf(lg[e] - m); s += p[e]; }
    float inv = 1.f / s;
#pragma unroll
    for (int e = 0; e < Ee; e++) p[e] *= inv;

    int i1 = 0;
#pragma unroll
    for (int e = 1; e < Ee; e++) if (p[e] > p[i1]) i1 = e;
    int i2 = (i1 == 0) ? 1 : 0;
#pragma unroll
    for (int e = 0; e < Ee; e++) if (e != i1 && p[e] > p[i2]) i2 = e;

    int t = b*Vv + v0 + tid;
    g_sel[2*t + 0] = i1;  g_wsel[2*t + 0] = p[i1];
    g_sel[2*t + 1] = i2;  g_wsel[2*t + 1] = p[i2];
    atomicAdd(&g_counts[i1], 1);
    atomicAdd(&g_counts[i2], 1);
}

// ---------------- K2: plan tiles; re-zero counters ----------------
__global__ void k2_plan() {
    if (threadIdx.x != 0 || blockIdx.x != 0) return;
    int base = 0, nt = 0;
    for (int e = 0; e < Ee; e++) {
        int cnt = g_counts[e];
        g_counts[e] = 0;
        g_cursor[e] = base;
        int t = (cnt + TILE_M - 1) / TILE_M;
        for (int i = 0; i < t; i++) { g_tile_e[nt] = e; g_tile_r0[nt] = base + i*TILE_M; nt++; }
        for (int pq = base + cnt; pq < base + t*TILE_M; pq++) g_rows[pq] = -1;
        base += t*TILE_M;
    }
    g_ntiles = nt;
}

// ---------------- K3: block-aggregated scatter ----------------
__global__ void k3_scatter() {
    __shared__ int hcnt[Ee];
    __shared__ int hbase[Ee];
    const int tid = threadIdx.x;
    const int t = blockIdx.x * blockDim.x + tid;
    if (tid < Ee) hcnt[tid] = 0;
    __syncthreads();
    int e1 = 0, e2 = 0, p1 = 0, p2 = 0;
    float w1 = 0.f, w2 = 0.f;
    if (t < NTOK) {
        e1 = g_sel[2*t + 0];  w1 = g_wsel[2*t + 0];
        e2 = g_sel[2*t + 1];  w2 = g_wsel[2*t + 1];
        p1 = atomicAdd(&hcnt[e1], 1);
        p2 = atomicAdd(&hcnt[e2], 1);
    }
    __syncthreads();
    if (tid < Ee) hbase[tid] = atomicAdd(&g_cursor[tid], hcnt[tid]);
    __syncthreads();
    if (t < NTOK) {
        int q1 = hbase[e1] + p1;
        int q2 = hbase[e2] + p2;
        g_rows[q1] = 2*t + 0;  g_roww[q1] = w1;
        g_rows[q2] = 2*t + 1;  g_roww[q2] = w2;
    }
}

// ---------------- K4: grouped GEMM, fp16 m16n8k16 + ldmatrix, swizzled 3-stage, 2 CTAs/SM ----------------
__global__ __launch_bounds__(256, 2) void k4_gemm(const float* __restrict__ be) {
    const int mt = blockIdx.y;
    if (mt >= g_ntiles) return;
    const int o0 = blockIdx.x * TILE_N;

    extern __shared__ __align__(128) char sm[];   // NSTAGE * STAGE_BYTES
    __shared__ int   sTok[TILE_M];
    __shared__ float sW[TILE_M];
    __shared__ float sBias[TILE_N];

    const int tid  = threadIdx.x;
    const int lane = tid & 31, w = tid >> 5;
    const int wm = w & 3, wn = w >> 2;          // 4(M) x 2(N); warp tile 32 x 72
    const int g  = lane >> 2, tg = lane & 3;

    const int e  = g_tile_e[mt];
    const int r0 = g_tile_r0[mt];
    const __half* WeE = g_Weh + (size_t)e*Oo*Dd;

    if (tid < TILE_M) { sTok[tid] = g_rows[r0 + tid]; sW[tid] = g_roww[r0 + tid]; }
    if (tid < TILE_N) sBias[tid] = be[e*Oo + o0 + tid];
    __syncthreads();

    // swizzled stage loader: row r (128B = 64 halves), unit u (16B) -> r*128 + ((u^(r&7))<<4)
    auto load_stage = [&](int kc, int st) {
        char* As = sm + st*STAGE_BYTES;
        char* Bs = As + B_OFF;
        const int kb = kc*KCH;
#pragma unroll
        for (int j = 0; j < 4; j++) {             // A: 128 rows x 8 units
            int q = tid + j*256;
            int r = q >> 3, u = q & 7;
            int tk = sTok[r];
            const __half* src = (tk >= 0) ? (g_XTh + (size_t)(tk >> 1)*Dd + kb + u*8) : g_XTh;
            cp16(As + r*128 + ((u ^ (r & 7)) << 4), src, tk >= 0);
        }
#pragma unroll
        for (int j = 0; j < 5; j++) {             // B: 144 rows x 8 units
            int q = tid + j*256;
            if (q < TILE_N*8) {
                int r = q >> 3, u = q & 7;
                cp16(Bs + r*128 + ((u ^ (r & 7)) << 4),
                     WeE + (size_t)(o0 + r)*Dd + kb + u*8, true);
            }
        }
    };

    // ---- per-lane ldmatrix row bases + swizzle keys (identical pattern to tf32 version;
    //      16B unit now = 8 halves = half of a K16 step) ----
    const uint32_t sm0 = (uint32_t)__cvta_generic_to_shared(sm);
    const int rA = lane & 7;
    const int aRowSel = ((lane >> 3) & 1) * 8;    // A tiles 1,3 -> +8 rows
    const uint32_t uhA = (lane >> 4) << 4;        // A tiles 2,3 -> +1 unit (k+8)
    uint32_t aRowOff[2], aXor[2];
#pragma unroll
    for (int mf = 0; mf < 2; mf++) {
        int row = wm*32 + mf*16 + aRowSel + rA;
        aRowOff[mf] = sm0 + row*128;
        aXor[mf] = (uint32_t)((row & 7) << 4);
    }
    const int bRowSel = (lane >> 4) * 8;          // B tiles 2,3 -> +8 rows (next nf)
    const uint32_t uhB = ((lane >> 3) & 1) << 4;  // B tiles 1,3 -> +1 unit (k+8)
    uint32_t bRowOff[4], bXor[4];
#pragma unroll
    for (int p = 0; p < 4; p++) {
        int row = wn*72 + p*16 + bRowSel + rA;
        bRowOff[p] = sm0 + B_OFF + row*128;
        bXor[p] = (uint32_t)((row & 7) << 4);
    }
    uint32_t b8RowOff, b8Xor;
    {
        int row = wn*72 + 64 + rA;
        b8RowOff = sm0 + B_OFF + row*128;
        b8Xor = (uint32_t)((row & 7) << 4);
    }

    float acc[2][9][4];
#pragma unroll
    for (int mf = 0; mf < 2; mf++)
#pragma unroll
        for (int nf = 0; nf < 9; nf++)
#pragma unroll
            for (int i = 0; i < 4; i++) acc[mf][nf][i] = 0.f;

    load_stage(0, 0);
    asm volatile("cp.async.commit_group;\n");
    load_stage(1, 1);
    asm volatile("cp.async.commit_group;\n");

    for (int kc = 0; kc < NKCHUNK; kc++) {
        const int st = kc % NSTAGE;
        asm volatile("cp.async.wait_group 1;\n");   // stage kc complete; kc+1 may fly
        __syncthreads();

        if (kc + 2 < NKCHUNK) load_stage(kc + 2, (kc + 2) % NSTAGE);
        asm volatile("cp.async.commit_group;\n");

        const uint32_t stOff = (uint32_t)(st*STAGE_BYTES);

#pragma unroll
        for (int ks = 0; ks < 4; ks++) {            // 4 x K16 = K64 per chunk
            const uint32_t kuA = uhA + ks*32;       // 32 B = 16 halves
            const uint32_t kuB = uhB + ks*32;
            uint32_t a[2][4], bf[9][2];
#pragma unroll
            for (int p = 0; p < 4; p++)
                ldsm4(bf[2*p][0], bf[2*p][1], bf[2*p+1][0], bf[2*p+1][1],
                      bRowOff[p] + stOff + (kuB ^ bXor[p]));
            ldsm2(bf[8][0], bf[8][1], b8RowOff + stOff + (kuB ^ b8Xor));
#pragma unroll
            for (int mf = 0; mf < 2; mf++)
                ldsm4(a[mf][0], a[mf][1], a[mf][2], a[mf][3],
                      aRowOff[mf] + stOff + (kuA ^ aXor[mf]));

#pragma unroll
            for (int mf = 0; mf < 2; mf++)
#pragma unroll
                for (int nf = 0; nf < 9; nf++) {
                    float* c = acc[mf][nf];
                    asm volatile(
                        "mma.sync.aligned.m16n8k16.row.col.f32.f16.f16.f32 "
                        "{%0,%1,%2,%3}, {%4,%5,%6,%7}, {%8,%9}, {%0,%1,%2,%3};\n"
                        : "+f"(c[0]), "+f"(c[1]), "+f"(c[2]), "+f"(c[3])
                        : "r"(a[mf][0]), "r"(a[mf][1]), "r"(a[mf][2]), "r"(a[mf][3]),
                          "r"(bf[nf][0]), "r"(bf[nf][1]));
                }
        }
    }

    // epilogue: out = coef * (acc + bias) into slot-partial buffers (deterministic)
#pragma unroll
    for (int mf = 0; mf < 2; mf++) {
#pragma unroll
        for (int nf = 0; nf < 9; nf++) {
            int c = wn*72 + nf*8 + tg*2;
            int o = o0 + c;
#pragma unroll
            for (int h = 0; h < 2; h++) {
                int r = wm*32 + mf*16 + g + h*8;
                int tk = sTok[r];
                if (tk < 0) continue;
                float wv = sW[r];
                float2 v;
                v.x = wv * (acc[mf][nf][h*2 + 0] + sBias[c]);
                v.y = wv * (acc[mf][nf][h*2 + 1] + sBias[c + 1]);
                *(float2*)(&g_part[tk & 1][(size_t)(tk >> 1)*Oo + o]) = v;
            }
        }
    }
}

// ---------------- K5: sum slot partials + transpose [B,V,O] -> [B,O,V] ----------------
__global__ void k5_out(float* __restrict__ out) {
    __shared__ float s[32][33];
    const int b = blockIdx.z, v0 = blockIdx.x*32, o0 = blockIdx.y*32;
    const int tx = threadIdx.x, ty = threadIdx.y;
#pragma unroll
    for (int i = 0; i < 4; i++) {
        int vy = ty + i*8;
        int o = o0 + tx;
        if (o < Oo) {
            size_t idx = (size_t)(b*Vv + v0 + vy)*Oo + o;
            s[vy][tx] = g_part[0][idx] + g_part[1][idx];
        }
    }
    __syncthreads();
#pragma unroll
    for (int i = 0; i < 4; i++) {
        int oy = ty + i*8;
        if (o0 + oy < Oo)
            out[((size_t)b*Oo + o0 + oy)*Vv + v0 + tx] = s[tx][oy];
    }
}

// ---------------- launch ----------------
extern "C" void kernel_launch(void* const* d_in, const int* in_sizes, int n_in,
                              void* d_out, int out_size) {
    const float* x  = (const float*)d_in[0];
    const float* Wg = (const float*)d_in[1];
    const float* We = (const float*)d_in[2];
    const float* be = (const float*)d_in[3];
    float* out = (float*)d_out;

    static int smem_set = 0;
    const int k4_smem = NSTAGE * STAGE_BYTES;   // 104448 B
    if (!smem_set) {
        cudaFuncSetAttribute(k4_gemm, cudaFuncAttributeMaxDynamicSharedMemorySize, k4_smem);
        smem_set = 1;
    }

    k0_prep<<<(Ee*Oo*Dd + 1023)/1024, 1024>>>(We);
    k1_gate<<<dim3(Vv/128, Bb), 128>>>(x, Wg);
    k2_plan<<<1, 32>>>();
    k3_scatter<<<(NTOK + 255)/256, 256>>>();
    k4_gemm<<<dim3(5, MAX_TILES), 256, k4_smem>>>(be);
    k5_out<<<dim3(Vv/32, (Oo + 31)/32, Bb), dim3(32, 8)>>>(out);
}

// round 10
// speedup vs baseline: 2.2651x; 1.0735x over previous
#include <cuda_runtime.h>
#include <cuda_fp16.h>
#include <math.h>
#include <stdint.h>

// Problem constants
#define Bb   64
#define Dd   512
#define Vv   512
#define Oo   720
#define Ee   8
#define NTOK    (Bb*Vv)        // 32768 tokens
#define NASSIGN (NTOK*2)       // 65536 assignments (top_k = 2)
#define TILE_M  128
#define TILE_N  144            // 720 = 5 * 144
#define MAX_TILES (NASSIGN/TILE_M + Ee)   // 520
#define ROWS_CAP  (MAX_TILES*TILE_M)
#define NSTAGE 3
#define KCH   64               // K elements per chunk (fp16: 128 B rows)
#define NKCHUNK (Dd/KCH)       // 8
// swizzled stage: (128+144) rows x 128 B
#define STAGE_BYTES ((TILE_M + TILE_N) * 128)   // 34816
#define B_OFF (TILE_M*128)                      // 16384

// ---------------- static device scratch ----------------
__device__ __half g_XTh[NTOK*Dd];        // tokens [B*V][D], fp16
__device__ __half g_Weh[Ee*Oo*Dd];       // expert weights, fp16
__device__ __half g_parth[2][NTOK*Oo];   // per-slot partial outputs (fp16)
__device__ int    g_rows[ROWS_CAP];
__device__ float  g_roww[ROWS_CAP];
__device__ int    g_counts[Ee];          // zero-init; k2 re-zeros each call
__device__ int    g_cursor[Ee];
__device__ int    g_tile_e[MAX_TILES];
__device__ int    g_tile_r0[MAX_TILES];
__device__ int    g_ntiles;
__device__ int    g_sel[NASSIGN];
__device__ float  g_wsel[NASSIGN];

__device__ __forceinline__ void cp16(void* smem_ptr, const void* gptr, bool valid) {
    uint32_t saddr = (uint32_t)__cvta_generic_to_shared(smem_ptr);
    int sz = valid ? 16 : 0;
    asm volatile("cp.async.cg.shared.global [%0], [%1], 16, %2;\n"
                 :: "r"(saddr), "l"(gptr), "r"(sz));
}
__device__ __forceinline__ void ldsm4(uint32_t& r0, uint32_t& r1, uint32_t& r2, uint32_t& r3,
                                      uint32_t addr) {
    asm volatile("ldmatrix.sync.aligned.m8n8.x4.shared.b16 {%0,%1,%2,%3}, [%4];"
                 : "=r"(r0), "=r"(r1), "=r"(r2), "=r"(r3) : "r"(addr));
}
__device__ __forceinline__ void ldsm2(uint32_t& r0, uint32_t& r1, uint32_t addr) {
    asm volatile("ldmatrix.sync.aligned.m8n8.x2.shared.b16 {%0,%1}, [%2];"
                 : "=r"(r0), "=r"(r1) : "r"(addr));
}

// ---------------- K0: convert We to fp16 ----------------
__global__ void k0_prep(const float* __restrict__ We) {
    int i = blockIdx.x * blockDim.x + threadIdx.x;
    if (i < Ee*Oo*Dd) g_Weh[i] = __float2half(We[i]);
}

// ---------------- K1: fused transpose + gating + softmax + top-2 ----------------
__global__ void k1_gate(const float* __restrict__ x, const float* __restrict__ Wg) {
    __shared__ float sWg[Ee*Dd];
    __shared__ float sX[32][129];
    const int b  = blockIdx.y;
    const int v0 = blockIdx.x * 128;
    const int tid = threadIdx.x;
    const int wq = tid >> 5, lane = tid & 31;

    for (int i = tid; i < Ee*Dd; i += 128) sWg[i] = Wg[i];
    __syncthreads();

    float lg[Ee];
#pragma unroll
    for (int e = 0; e < Ee; e++) lg[e] = 0.f;

    for (int dc = 0; dc < Dd/32; dc++) {
#pragma unroll
        for (int i = 0; i < 32; i++)
            sX[i][tid] = x[((size_t)b*Dd + dc*32 + i)*Vv + v0 + tid];
        __syncthreads();
#pragma unroll
        for (int i = 0; i < 32; i++) {
            float xv = sX[i][tid];
            int d = dc*32 + i;
#pragma unroll
            for (int e = 0; e < Ee; e++) lg[e] += xv * sWg[e*Dd + d];
        }
#pragma unroll
        for (int r = 0; r < 32; r++) {
            int v = wq*32 + r;
            g_XTh[((size_t)(b*Vv + v0 + v))*Dd + dc*32 + lane] = __float2half(sX[lane][v]);
        }
        __syncthreads();
    }

    float m = lg[0];
#pragma unroll
    for (int e = 1; e < Ee; e++) m = fmaxf(m, lg[e]);
    float p[Ee], s = 0.f;
#pragma unroll
    for (int e = 0; e < Ee; e++) { p[e] = expf(lg[e] - m); s += p[e]; }
    float inv = 1.f / s;
#pragma unroll
    for (int e = 0; e < Ee; e++) p[e] *= inv;

    int i1 = 0;
#pragma unroll
    for (int e = 1; e < Ee; e++) if (p[e] > p[i1]) i1 = e;
    int i2 = (i1 == 0) ? 1 : 0;
#pragma unroll
    for (int e = 0; e < Ee; e++) if (e != i1 && p[e] > p[i2]) i2 = e;

    int t = b*Vv + v0 + tid;
    g_sel[2*t + 0] = i1;  g_wsel[2*t + 0] = p[i1];
    g_sel[2*t + 1] = i2;  g_wsel[2*t + 1] = p[i2];
    atomicAdd(&g_counts[i1], 1);
    atomicAdd(&g_counts[i2], 1);
}

// ---------------- K2: plan tiles (parallel); re-zero counters ----------------
__global__ void k2_plan() {
    __shared__ int sBase[Ee], sCnt[Ee], sT[Ee], sTB[Ee];
    const int tid = threadIdx.x;
    if (tid == 0) {
        int base = 0, nt = 0;
        for (int e = 0; e < Ee; e++) {
            int cnt = g_counts[e];
            g_counts[e] = 0;
            sCnt[e] = cnt;
            sBase[e] = base;
            g_cursor[e] = base;
            int t = (cnt + TILE_M - 1) / TILE_M;
            sT[e] = t;  sTB[e] = nt;
            nt += t;
            base += t*TILE_M;
        }
        g_ntiles = nt;
    }
    __syncthreads();
#pragma unroll
    for (int e = 0; e < Ee; e++) {
        for (int i = tid; i < sT[e]; i += blockDim.x) {
            g_tile_e[sTB[e] + i]  = e;
            g_tile_r0[sTB[e] + i] = sBase[e] + i*TILE_M;
        }
        int pstart = sBase[e] + sCnt[e];
        int pend   = sBase[e] + sT[e]*TILE_M;
        for (int p = pstart + tid; p < pend; p += blockDim.x) g_rows[p] = -1;
    }
}

// ---------------- K3: block-aggregated scatter ----------------
__global__ void k3_scatter() {
    __shared__ int hcnt[Ee];
    __shared__ int hbase[Ee];
    const int tid = threadIdx.x;
    const int t = blockIdx.x * blockDim.x + tid;
    if (tid < Ee) hcnt[tid] = 0;
    __syncthreads();
    int e1 = 0, e2 = 0, p1 = 0, p2 = 0;
    float w1 = 0.f, w2 = 0.f;
    if (t < NTOK) {
        e1 = g_sel[2*t + 0];  w1 = g_wsel[2*t + 0];
        e2 = g_sel[2*t + 1];  w2 = g_wsel[2*t + 1];
        p1 = atomicAdd(&hcnt[e1], 1);
        p2 = atomicAdd(&hcnt[e2], 1);
    }
    __syncthreads();
    if (tid < Ee) hbase[tid] = atomicAdd(&g_cursor[tid], hcnt[tid]);
    __syncthreads();
    if (t < NTOK) {
        int q1 = hbase[e1] + p1;
        int q2 = hbase[e2] + p2;
        g_rows[q1] = 2*t + 0;  g_roww[q1] = w1;
        g_rows[q2] = 2*t + 1;  g_roww[q2] = w2;
    }
}

// ---------------- K4: grouped GEMM, fp16 m16n8k16 + ldmatrix, swizzled 3-stage, 2 CTAs/SM ----------------
__global__ __launch_bounds__(256, 2) void k4_gemm(const float* __restrict__ be) {
    const int mt = blockIdx.y;
    if (mt >= g_ntiles) return;
    const int o0 = blockIdx.x * TILE_N;

    extern __shared__ __align__(128) char sm[];   // NSTAGE * STAGE_BYTES
    __shared__ int   sTok[TILE_M];
    __shared__ float sW[TILE_M];
    __shared__ float sBias[TILE_N];

    const int tid  = threadIdx.x;
    const int lane = tid & 31, w = tid >> 5;
    const int wm = w & 3, wn = w >> 2;          // 4(M) x 2(N); warp tile 32 x 72
    const int g  = lane >> 2, tg = lane & 3;

    const int e  = g_tile_e[mt];
    const int r0 = g_tile_r0[mt];
    const __half* WeE = g_Weh + (size_t)e*Oo*Dd;

    if (tid < TILE_M) { sTok[tid] = g_rows[r0 + tid]; sW[tid] = g_roww[r0 + tid]; }
    if (tid < TILE_N) sBias[tid] = be[e*Oo + o0 + tid];
    __syncthreads();

    // swizzled stage loader: row r (128B = 64 halves), unit u (16B) -> r*128 + ((u^(r&7))<<4)
    auto load_stage = [&](int kc, int st) {
        char* As = sm + st*STAGE_BYTES;
        char* Bs = As + B_OFF;
        const int kb = kc*KCH;
#pragma unroll
        for (int j = 0; j < 4; j++) {             // A: 128 rows x 8 units
            int q = tid + j*256;
            int r = q >> 3, u = q & 7;
            int tk = sTok[r];
            const __half* src = (tk >= 0) ? (g_XTh + (size_t)(tk >> 1)*Dd + kb + u*8) : g_XTh;
            cp16(As + r*128 + ((u ^ (r & 7)) << 4), src, tk >= 0);
        }
#pragma unroll
        for (int j = 0; j < 5; j++) {             // B: 144 rows x 8 units
            int q = tid + j*256;
            if (q < TILE_N*8) {
                int r = q >> 3, u = q & 7;
                cp16(Bs + r*128 + ((u ^ (r & 7)) << 4),
                     WeE + (size_t)(o0 + r)*Dd + kb + u*8, true);
            }
        }
    };

    // ---- per-lane ldmatrix row bases + swizzle keys ----
    const uint32_t sm0 = (uint32_t)__cvta_generic_to_shared(sm);
    const int rA = lane & 7;
    const int aRowSel = ((lane >> 3) & 1) * 8;    // A tiles 1,3 -> +8 rows
    const uint32_t uhA = (lane >> 4) << 4;        // A tiles 2,3 -> +1 unit (k+8)
    uint32_t aRowOff[2], aXor[2];
#pragma unroll
    for (int mf = 0; mf < 2; mf++) {
        int row = wm*32 + mf*16 + aRowSel + rA;
        aRowOff[mf] = sm0 + row*128;
        aXor[mf] = (uint32_t)((row & 7) << 4);
    }
    const int bRowSel = (lane >> 4) * 8;          // B tiles 2,3 -> +8 rows (next nf)
    const uint32_t uhB = ((lane >> 3) & 1) << 4;  // B tiles 1,3 -> +1 unit (k+8)
    uint32_t bRowOff[4], bXor[4];
#pragma unroll
    for (int p = 0; p < 4; p++) {
        int row = wn*72 + p*16 + bRowSel + rA;
        bRowOff[p] = sm0 + B_OFF + row*128;
        bXor[p] = (uint32_t)((row & 7) << 4);
    }
    uint32_t b8RowOff, b8Xor;
    {
        int row = wn*72 + 64 + rA;
        b8RowOff = sm0 + B_OFF + row*128;
        b8Xor = (uint32_t)((row & 7) << 4);
    }

    float acc[2][9][4];
#pragma unroll
    for (int mf = 0; mf < 2; mf++)
#pragma unroll
        for (int nf = 0; nf < 9; nf++)
#pragma unroll
            for (int i = 0; i < 4; i++) acc[mf][nf][i] = 0.f;

    load_stage(0, 0);
    asm volatile("cp.async.commit_group;\n");
    load_stage(1, 1);
    asm volatile("cp.async.commit_group;\n");

    for (int kc = 0; kc < NKCHUNK; kc++) {
        const int st = kc % NSTAGE;
        asm volatile("cp.async.wait_group 1;\n");   // stage kc complete; kc+1 may fly
        __syncthreads();

        if (kc + 2 < NKCHUNK) load_stage(kc + 2, (kc + 2) % NSTAGE);
        asm volatile("cp.async.commit_group;\n");

        const uint32_t stOff = (uint32_t)(st*STAGE_BYTES);

#pragma unroll
        for (int ks = 0; ks < 4; ks++) {            // 4 x K16 = K64 per chunk
            const uint32_t kuA = uhA + ks*32;       // 32 B = 16 halves
            const uint32_t kuB = uhB + ks*32;
            uint32_t a[2][4], bf[9][2];
#pragma unroll
            for (int p = 0; p < 4; p++)
                ldsm4(bf[2*p][0], bf[2*p][1], bf[2*p+1][0], bf[2*p+1][1],
                      bRowOff[p] + stOff + (kuB ^ bXor[p]));
            ldsm2(bf[8][0], bf[8][1], b8RowOff + stOff + (kuB ^ b8Xor));
#pragma unroll
            for (int mf = 0; mf < 2; mf++)
                ldsm4(a[mf][0], a[mf][1], a[mf][2], a[mf][3],
                      aRowOff[mf] + stOff + (kuA ^ aXor[mf]));

#pragma unroll
            for (int mf = 0; mf < 2; mf++)
#pragma unroll
                for (int nf = 0; nf < 9; nf++) {
                    float* c = acc[mf][nf];
                    asm volatile(
                        "mma.sync.aligned.m16n8k16.row.col.f32.f16.f16.f32 "
                        "{%0,%1,%2,%3}, {%4,%5,%6,%7}, {%8,%9}, {%0,%1,%2,%3};\n"
                        : "+f"(c[0]), "+f"(c[1]), "+f"(c[2]), "+f"(c[3])
                        : "r"(a[mf][0]), "r"(a[mf][1]), "r"(a[mf][2]), "r"(a[mf][3]),
                          "r"(bf[nf][0]), "r"(bf[nf][1]));
                }
        }
    }

    // epilogue: out = coef * (acc + bias), packed half2 into slot-partial buffers
#pragma unroll
    for (int mf = 0; mf < 2; mf++) {
#pragma unroll
        for (int nf = 0; nf < 9; nf++) {
            int c = wn*72 + nf*8 + tg*2;
            int o = o0 + c;
#pragma unroll
            for (int h = 0; h < 2; h++) {
                int r = wm*32 + mf*16 + g + h*8;
                int tk = sTok[r];
                if (tk < 0) continue;
                float wv = sW[r];
                float vx = wv * (acc[mf][nf][h*2 + 0] + sBias[c]);
                float vy = wv * (acc[mf][nf][h*2 + 1] + sBias[c + 1]);
                *(__half2*)(&g_parth[tk & 1][(size_t)(tk >> 1)*Oo + o]) =
                    __floats2half2_rn(vx, vy);
            }
        }
    }
}

// ---------------- K5: sum fp16 slot partials + transpose [B,V,O] -> [B,O,V] ----------------
__global__ void k5_out(float* __restrict__ out) {
    __shared__ float s[32][33];
    const int b = blockIdx.z, v0 = blockIdx.x*32, o0 = blockIdx.y*32;
    const int tx = threadIdx.x, ty = threadIdx.y;
#pragma unroll
    for (int i = 0; i < 4; i++) {
        int vy = ty + i*8;
        int o = o0 + tx;
        if (o < Oo) {
            size_t idx = (size_t)(b*Vv + v0 + vy)*Oo + o;
            s[vy][tx] = __half2float(g_parth[0][idx]) + __half2float(g_parth[1][idx]);
        }
    }
    __syncthreads();
#pragma unroll
    for (int i = 0; i < 4; i++) {
        int oy = ty + i*8;
        if (o0 + oy < Oo)
            out[((size_t)b*Oo + o0 + oy)*Vv + v0 + tx] = s[tx][oy];
    }
}

// ---------------- launch ----------------
extern "C" void kernel_launch(void* const* d_in, const int* in_sizes, int n_in,
                              void* d_out, int out_size) {
    const float* x  = (const float*)d_in[0];
    const float* Wg = (const float*)d_in[1];
    const float* We = (const float*)d_in[2];
    const float* be = (const float*)d_in[3];
    float* out = (float*)d_out;

    static int smem_set = 0;
    const int k4_smem = NSTAGE * STAGE_BYTES;   // 104448 B
    if (!smem_set) {
        cudaFuncSetAttribute(k4_gemm, cudaFuncAttributeMaxDynamicSharedMemorySize, k4_smem);
        smem_set = 1;
    }

    k0_prep<<<(Ee*Oo*Dd + 1023)/1024, 1024>>>(We);
    k1_gate<<<dim3(Vv/128, Bb), 128>>>(x, Wg);
    k2_plan<<<1, 256>>>();
    k3_scatter<<<(NTOK + 255)/256, 256>>>();
    k4_gemm<<<dim3(5, MAX_TILES), 256, k4_smem>>>(be);
    k5_out<<<dim3(Vv/32, (Oo + 31)/32, Bb), dim3(32, 8)>>>(out);
}

// round 11
// speedup vs baseline: 2.3553x; 1.0398x over previous
#include <cuda_runtime.h>
#include <cuda_fp16.h>
#include <math.h>
#include <stdint.h>

// Problem constants
#define Bb   64
#define Dd   512
#define Vv   512
#define Oo   720
#define Ee   8
#define NTOK    (Bb*Vv)        // 32768 tokens
#define NASSIGN (NTOK*2)       // 65536 assignments (top_k = 2)
#define TILE_M  128
#define TILE_N  144            // 720 = 5 * 144
#define MAX_TILES (NASSIGN/TILE_M + Ee)   // 520
#define ROWS_CAP  (MAX_TILES*TILE_M)
#define NSTAGE 3
#define KCH   64               // K elements per chunk (fp16: 128 B rows)
#define NKCHUNK (Dd/KCH)       // 8
// swizzled stage: (128+144) rows x 128 B
#define STAGE_BYTES ((TILE_M + TILE_N) * 128)   // 34816
#define B_OFF (TILE_M*128)                      // 16384

// ---------------- static device scratch ----------------
__device__ __half g_XTh[NTOK*Dd];        // tokens [B*V][D], fp16
__device__ __half g_Weh[Ee*Oo*Dd];       // expert weights, fp16
__device__ __half g_parth[2][NTOK*Oo];   // per-slot partial outputs (fp16)
__device__ int    g_rows[ROWS_CAP];
__device__ float  g_roww[ROWS_CAP];
__device__ int    g_counts[Ee];          // zero-init; k2 re-zeros each call
__device__ int    g_cursor[Ee];
__device__ int    g_tile_e[MAX_TILES];
__device__ int    g_tile_r0[MAX_TILES];
__device__ int    g_ntiles;
__device__ int    g_sel[NASSIGN];
__device__ float  g_wsel[NASSIGN];

__device__ __forceinline__ void cp16(void* smem_ptr, const void* gptr, bool valid) {
    uint32_t saddr = (uint32_t)__cvta_generic_to_shared(smem_ptr);
    int sz = valid ? 16 : 0;
    asm volatile("cp.async.cg.shared.global [%0], [%1], 16, %2;\n"
                 :: "r"(saddr), "l"(gptr), "r"(sz));
}
__device__ __forceinline__ void ldsm4(uint32_t& r0, uint32_t& r1, uint32_t& r2, uint32_t& r3,
                                      uint32_t addr) {
    asm volatile("ldmatrix.sync.aligned.m8n8.x4.shared.b16 {%0,%1,%2,%3}, [%4];"
                 : "=r"(r0), "=r"(r1), "=r"(r2), "=r"(r3) : "r"(addr));
}
__device__ __forceinline__ void ldsm2(uint32_t& r0, uint32_t& r1, uint32_t addr) {
    asm volatile("ldmatrix.sync.aligned.m8n8.x2.shared.b16 {%0,%1}, [%2];"
                 : "=r"(r0), "=r"(r1) : "r"(addr));
}

// ---------------- K0: convert We to fp16 ----------------
__global__ void k0_prep(const float* __restrict__ We) {
    int i = blockIdx.x * blockDim.x + threadIdx.x;
    if (i < Ee*Oo*Dd) g_Weh[i] = __float2half(We[i]);
}

// ---------------- K1: fused transpose + gating + softmax + top-2 (64-d rounds, half2 stores) ----------------
__global__ void k1_gate(const float* __restrict__ x, const float* __restrict__ Wg) {
    __shared__ float sWg[Ee*Dd];          // 16 KB
    __shared__ float sX[64][129];         // 33 KB
    const int b  = blockIdx.y;
    const int v0 = blockIdx.x * 128;
    const int tid = threadIdx.x;
    const int wq = tid >> 5, lane = tid & 31;

    for (int i = tid; i < Ee*Dd; i += 128) sWg[i] = Wg[i];
    __syncthreads();

    float lg[Ee];
#pragma unroll
    for (int e = 0; e < Ee; e++) lg[e] = 0.f;

    for (int dc = 0; dc < Dd/64; dc++) {
        const int d0 = dc*64;
#pragma unroll
        for (int i = 0; i < 64; i++)
            sX[i][tid] = x[((size_t)b*Dd + d0 + i)*Vv + v0 + tid];
        __syncthreads();
#pragma unroll
        for (int i = 0; i < 64; i++) {
            float xv = sX[i][tid];
#pragma unroll
            for (int e = 0; e < Ee; e++) lg[e] += xv * sWg[e*Dd + d0 + i];
        }
        // transpose-write XT as half2 (128 B coalesced rows)
#pragma unroll
        for (int r = 0; r < 32; r++) {
            int v = wq*32 + r;
            __half2 h = __floats2half2_rn(sX[lane*2][v], sX[lane*2 + 1][v]);
            *(__half2*)(&g_XTh[((size_t)(b*Vv + v0 + v))*Dd + d0 + lane*2]) = h;
        }
        __syncthreads();
    }

    float m = lg[0];
#pragma unroll
    for (int e = 1; e < Ee; e++) m = fmaxf(m, lg[e]);
    float p[Ee], s = 0.f;
#pragma unroll
    for (int e = 0; e < Ee; e++) { p[e] = expf(lg[e] - m); s += p[e]; }
    float inv = 1.f / s;
#pragma unroll
    for (int e = 0; e < Ee; e++) p[e] *= inv;

    int i1 = 0;
#pragma unroll
    for (int e = 1; e < Ee; e++) if (p[e] > p[i1]) i1 = e;
    int i2 = (i1 == 0) ? 1 : 0;
#pragma unroll
    for (int e = 0; e < Ee; e++) if (e != i1 && p[e] > p[i2]) i2 = e;

    int t = b*Vv + v0 + tid;
    g_sel[2*t + 0] = i1;  g_wsel[2*t + 0] = p[i1];
    g_sel[2*t + 1] = i2;  g_wsel[2*t + 1] = p[i2];
    atomicAdd(&g_counts[i1], 1);
    atomicAdd(&g_counts[i2], 1);
}

// ---------------- K2: plan tiles (parallel); re-zero counters ----------------
__global__ void k2_plan() {
    __shared__ int sBase[Ee], sCnt[Ee], sT[Ee], sTB[Ee];
    const int tid = threadIdx.x;
    if (tid == 0) {
        int base = 0, nt = 0;
        for (int e = 0; e < Ee; e++) {
            int cnt = g_counts[e];
            g_counts[e] = 0;
            sCnt[e] = cnt;
            sBase[e] = base;
            g_cursor[e] = base;
            int t = (cnt + TILE_M - 1) / TILE_M;
            sT[e] = t;  sTB[e] = nt;
            nt += t;
            base += t*TILE_M;
        }
        g_ntiles = nt;
    }
    __syncthreads();
#pragma unroll
    for (int e = 0; e < Ee; e++) {
        for (int i = tid; i < sT[e]; i += blockDim.x) {
            g_tile_e[sTB[e] + i]  = e;
            g_tile_r0[sTB[e] + i] = sBase[e] + i*TILE_M;
        }
        int pstart = sBase[e] + sCnt[e];
        int pend   = sBase[e] + sT[e]*TILE_M;
        for (int p = pstart + tid; p < pend; p += blockDim.x) g_rows[p] = -1;
    }
}

// ---------------- K3: block-aggregated scatter ----------------
__global__ void k3_scatter() {
    __shared__ int hcnt[Ee];
    __shared__ int hbase[Ee];
    const int tid = threadIdx.x;
    const int t = blockIdx.x * blockDim.x + tid;
    if (tid < Ee) hcnt[tid] = 0;
    __syncthreads();
    int e1 = 0, e2 = 0, p1 = 0, p2 = 0;
    float w1 = 0.f, w2 = 0.f;
    if (t < NTOK) {
        e1 = g_sel[2*t + 0];  w1 = g_wsel[2*t + 0];
        e2 = g_sel[2*t + 1];  w2 = g_wsel[2*t + 1];
        p1 = atomicAdd(&hcnt[e1], 1);
        p2 = atomicAdd(&hcnt[e2], 1);
    }
    __syncthreads();
    if (tid < Ee) hbase[tid] = atomicAdd(&g_cursor[tid], hcnt[tid]);
    __syncthreads();
    if (t < NTOK) {
        int q1 = hbase[e1] + p1;
        int q2 = hbase[e2] + p2;
        g_rows[q1] = 2*t + 0;  g_roww[q1] = w1;
        g_rows[q2] = 2*t + 1;  g_roww[q2] = w2;
    }
}

// ---------------- K4: grouped GEMM, fp16 m16n8k16 + ldmatrix, swizzled 3-stage, 2 CTAs/SM ----------------
__global__ __launch_bounds__(256, 2) void k4_gemm(const float* __restrict__ be) {
    const int mt = blockIdx.y;
    if (mt >= g_ntiles) return;
    const int o0 = blockIdx.x * TILE_N;

    extern __shared__ __align__(128) char sm[];   // NSTAGE * STAGE_BYTES
    __shared__ int   sTok[TILE_M];
    __shared__ float sW[TILE_M];
    __shared__ float sBias[TILE_N];

    const int tid  = threadIdx.x;
    const int lane = tid & 31, w = tid >> 5;
    const int wm = w & 3, wn = w >> 2;          // 4(M) x 2(N); warp tile 32 x 72
    const int g  = lane >> 2, tg = lane & 3;

    const int e  = g_tile_e[mt];
    const int r0 = g_tile_r0[mt];
    const __half* WeE = g_Weh + (size_t)e*Oo*Dd;

    if (tid < TILE_M) { sTok[tid] = g_rows[r0 + tid]; sW[tid] = g_roww[r0 + tid]; }
    if (tid < TILE_N) sBias[tid] = be[e*Oo + o0 + tid];
    __syncthreads();

    // swizzled stage loader: row r (128B = 64 halves), unit u (16B) -> r*128 + ((u^(r&7))<<4)
    auto load_stage = [&](int kc, int st) {
        char* As = sm + st*STAGE_BYTES;
        char* Bs = As + B_OFF;
        const int kb = kc*KCH;
#pragma unroll
        for (int j = 0; j < 4; j++) {             // A: 128 rows x 8 units
            int q = tid + j*256;
            int r = q >> 3, u = q & 7;
            int tk = sTok[r];
            const __half* src = (tk >= 0) ? (g_XTh + (size_t)(tk >> 1)*Dd + kb + u*8) : g_XTh;
            cp16(As + r*128 + ((u ^ (r & 7)) << 4), src, tk >= 0);
        }
#pragma unroll
        for (int j = 0; j < 5; j++) {             // B: 144 rows x 8 units
            int q = tid + j*256;
            if (q < TILE_N*8) {
                int r = q >> 3, u = q & 7;
                cp16(Bs + r*128 + ((u ^ (r & 7)) << 4),
                     WeE + (size_t)(o0 + r)*Dd + kb + u*8, true);
            }
        }
    };

    // ---- per-lane ldmatrix row bases + swizzle keys ----
    const uint32_t sm0 = (uint32_t)__cvta_generic_to_shared(sm);
    const int rA = lane & 7;
    const int aRowSel = ((lane >> 3) & 1) * 8;    // A tiles 1,3 -> +8 rows
    const uint32_t uhA = (lane >> 4) << 4;        // A tiles 2,3 -> +1 unit (k+8)
    uint32_t aRowOff[2], aXor[2];
#pragma unroll
    for (int mf = 0; mf < 2; mf++) {
        int row = wm*32 + mf*16 + aRowSel + rA;
        aRowOff[mf] = sm0 + row*128;
        aXor[mf] = (uint32_t)((row & 7) << 4);
    }
    const int bRowSel = (lane >> 4) * 8;          // B tiles 2,3 -> +8 rows (next nf)
    const uint32_t uhB = ((lane >> 3) & 1) << 4;  // B tiles 1,3 -> +1 unit (k+8)
    uint32_t bRowOff[4], bXor[4];
#pragma unroll
    for (int p = 0; p < 4; p++) {
        int row = wn*72 + p*16 + bRowSel + rA;
        bRowOff[p] = sm0 + B_OFF + row*128;
        bXor[p] = (uint32_t)((row & 7) << 4);
    }
    uint32_t b8RowOff, b8Xor;
    {
        int row = wn*72 + 64 + rA;
        b8RowOff = sm0 + B_OFF + row*128;
        b8Xor = (uint32_t)((row & 7) << 4);
    }

    float acc[2][9][4];
#pragma unroll
    for (int mf = 0; mf < 2; mf++)
#pragma unroll
        for (int nf = 0; nf < 9; nf++)
#pragma unroll
            for (int i = 0; i < 4; i++) acc[mf][nf][i] = 0.f;

    load_stage(0, 0);
    asm volatile("cp.async.commit_group;\n");
    load_stage(1, 1);
    asm volatile("cp.async.commit_group;\n");

    for (int kc = 0; kc < NKCHUNK; kc++) {
        const int st = kc % NSTAGE;
        asm volatile("cp.async.wait_group 1;\n");   // stage kc complete; kc+1 may fly
        __syncthreads();

        const uint32_t stOff = (uint32_t)(st*STAGE_BYTES);

#pragma unroll
        for (int ks = 0; ks < 4; ks++) {            // 4 x K16 = K64 per chunk
            const uint32_t kuA = uhA + ks*32;       // 32 B = 16 halves
            const uint32_t kuB = uhB + ks*32;
            uint32_t a[2][4], bf[9][2];
#pragma unroll
            for (int p = 0; p < 4; p++)
                ldsm4(bf[2*p][0], bf[2*p][1], bf[2*p+1][0], bf[2*p+1][1],
                      bRowOff[p] + stOff + (kuB ^ bXor[p]));
            ldsm2(bf[8][0], bf[8][1], b8RowOff + stOff + (kuB ^ b8Xor));
#pragma unroll
            for (int mf = 0; mf < 2; mf++)
                ldsm4(a[mf][0], a[mf][1], a[mf][2], a[mf][3],
                      aRowOff[mf] + stOff + (kuA ^ aXor[mf]));

#pragma unroll
            for (int mf = 0; mf < 2; mf++)
#pragma unroll
                for (int nf = 0; nf < 9; nf++) {
                    float* c = acc[mf][nf];
                    asm volatile(
                        "mma.sync.aligned.m16n8k16.row.col.f32.f16.f16.f32 "
                        "{%0,%1,%2,%3}, {%4,%5,%6,%7}, {%8,%9}, {%0,%1,%2,%3};\n"
                        : "+f"(c[0]), "+f"(c[1]), "+f"(c[2]), "+f"(c[3])
                        : "r"(a[mf][0]), "r"(a[mf][1]), "r"(a[mf][2]), "r"(a[mf][3]),
                          "r"(bf[nf][0]), "r"(bf[nf][1]));
                }

            // issue next-stage loads after the first mma batch is in flight
            if (ks == 0) {
                if (kc + 2 < NKCHUNK) load_stage(kc + 2, (kc + 2) % NSTAGE);
                asm volatile("cp.async.commit_group;\n");
            }
        }
    }

    // epilogue: out = coef * (acc + bias), packed half2 into slot-partial buffers
#pragma unroll
    for (int mf = 0; mf < 2; mf++) {
#pragma unroll
        for (int nf = 0; nf < 9; nf++) {
            int c = wn*72 + nf*8 + tg*2;
            int o = o0 + c;
#pragma unroll
            for (int h = 0; h < 2; h++) {
                int r = wm*32 + mf*16 + g + h*8;
                int tk = sTok[r];
                if (tk < 0) continue;
                float wv = sW[r];
                float vx = wv * (acc[mf][nf][h*2 + 0] + sBias[c]);
                float vy = wv * (acc[mf][nf][h*2 + 1] + sBias[c + 1]);
                *(__half2*)(&g_parth[tk & 1][(size_t)(tk >> 1)*Oo + o]) =
                    __floats2half2_rn(vx, vy);
            }
        }
    }
}

// ---------------- K5: sum fp16 slot partials + transpose [B,V,O] -> [B,O,V] (half2 loads) ----------------
// grid (V/32, ceil(O/64), B), block (32,8); tile 32 v x 64 o
__global__ void k5_out(float* __restrict__ out) {
    __shared__ float s[32][65];
    const int b = blockIdx.z, v0 = blockIdx.x*32, o0 = blockIdx.y*64;
    const int tx = threadIdx.x, ty = threadIdx.y;
#pragma unroll
    for (int i = 0; i < 4; i++) {
        int vy = ty + i*8;
        int o = o0 + 2*tx;
        if (o < Oo) {
            size_t idx = (size_t)(b*Vv + v0 + vy)*Oo + o;
            __half2 p0 = *(const __half2*)(&g_parth[0][idx]);
            __half2 p1 = *(const __half2*)(&g_parth[1][idx]);
            float2 f0 = __half22float2(p0), f1 = __half22float2(p1);
            s[vy][2*tx]     = f0.x + f1.x;
            s[vy][2*tx + 1] = f0.y + f1.y;
        }
    }
    __syncthreads();
#pragma unroll
    for (int j = 0; j < 8; j++) {
        int oy = ty + j*8;
        if (o0 + oy < Oo)
            out[((size_t)b*Oo + o0 + oy)*Vv + v0 + tx] = s[tx][oy];
    }
}

// ---------------- launch ----------------
extern "C" void kernel_launch(void* const* d_in, const int* in_sizes, int n_in,
                              void* d_out, int out_size) {
    const float* x  = (const float*)d_in[0];
    const float* Wg = (const float*)d_in[1];
    const float* We = (const float*)d_in[2];
    const float* be = (const float*)d_in[3];
    float* out = (float*)d_out;

    static int smem_set = 0;
    const int k4_smem = NSTAGE * STAGE_BYTES;   // 104448 B
    if (!smem_set) {
        cudaFuncSetAttribute(k4_gemm, cudaFuncAttributeMaxDynamicSharedMemorySize, k4_smem);
        smem_set = 1;
    }

    k0_prep<<<(Ee*Oo*Dd + 1023)/1024, 1024>>>(We);
    k1_gate<<<dim3(Vv/128, Bb), 128>>>(x, Wg);
    k2_plan<<<1, 256>>>();
    k3_scatter<<<(NTOK + 255)/256, 256>>>();
    k4_gemm<<<dim3(5, MAX_TILES), 256, k4_smem>>>(be);
    k5_out<<<dim3(Vv/32, (Oo + 63)/64, Bb), dim3(32, 8)>>>(out);
}